// round 14
// baseline (speedup 1.0000x reference)
#include <cuda_runtime.h>
#include <math.h>

#define BB 8
#define NBOX 300
#define RSEL 36
#define CCH 256
#define NROI (BB * RSEL)
#define IOU_THRS 0.7f
#define CONF_THRS 0.3f
#define GRIDP 14     // OUT*SR
#define NWORDS 10    // ceil(300/32)
#define MAXROWS 28
#define MAXSPAN 64
#define THREADS 256

// ---- per-ROI pooling plan + ready flags (device scratch; no allocs) ----
__device__ float g_wx[NROI][MAXSPAN];
__device__ int   g_rows[NROI][MAXROWS];
__device__ float g_rwt[NROI][MAXROWS];
__device__ int4  g_meta[NROI];        // {Kr, xmin, xmax, lv}
__device__ int   g_ready[BB];         // 0 at load; stays 1 after first launch
                                      // (safe: plan is deterministic, replays
                                      //  rewrite byte-identical values)

__device__ __forceinline__ float neg_inf() { return __int_as_float(0xff800000); }

__device__ __forceinline__ bool iou_gt(const float4 a, const float4 bb)
{
    float areaA = __fmul_rn(__fsub_rn(a.z, a.x), __fsub_rn(a.w, a.y));
    float areaB = __fmul_rn(__fsub_rn(bb.z, bb.x), __fsub_rn(bb.w, bb.y));
    float ltx = fmaxf(a.x, bb.x), lty = fmaxf(a.y, bb.y);
    float rbx = fminf(a.z, bb.z), rby = fminf(a.w, bb.w);
    float iw = fmaxf(__fsub_rn(rbx, ltx), 0.0f);
    float ih = fmaxf(__fsub_rn(rby, lty), 0.0f);
    float inter = __fmul_rn(iw, ih);
    float den = __fadd_rn(__fsub_rn(__fadd_rn(areaA, areaB), inter), 1e-9f);
    return __fdiv_rn(inter, den) > IOU_THRS;
}

// ---------------------------------------------------------------------------
// Single fused kernel. grid (RSEL, BB, 32), 256 threads.
// Blocks (r==0, z==0) do per-batch selection first (wave-1 resident by
// linear index), publish plan via fence+flag; all blocks then pool.
// ---------------------------------------------------------------------------
__global__ void __launch_bounds__(THREADS, 8)
fused_kernel(const float* __restrict__ boxes,
             const float* __restrict__ scores,
             const float* __restrict__ f0,
             const float* __restrict__ f1,
             const float* __restrict__ f2,
             const float* __restrict__ f3,
             float* __restrict__ out)
{
    const int r = blockIdx.x, b = blockIdx.y, z = blockIdx.z;
    const int tid = threadIdx.x;
    const int warp = tid >> 5, lane = tid & 31;

    // selection scratch (selector blocks only; smem is cheap on sm_103a)
    __shared__ float         s[NBOX];
    __shared__ float4        bx[NBOX];
    __shared__ unsigned char val[NBOX];
    __shared__ unsigned int  keepW[NWORDS];
    __shared__ float4 sselBox[RSEL];
    __shared__ int    sselLv[RSEL];
    __shared__ int    sselValid[RSEL];
    // pool scratch
    __shared__ float swx[MAXSPAN];
    __shared__ int   srows[MAXROWS];
    __shared__ float srwt[MAXROWS];
    __shared__ int4  smeta;

    if (r == 0 && z == 0) {
        // ================= selection (one block per batch) =================
        for (int i = tid; i < NBOX; i += THREADS) {
            float sc = scores[b * NBOX + i];
            s[i] = (sc > CONF_THRS) ? sc : neg_inf();
        }
        __syncthreads();

        // stable descending rank
        for (int box = tid; box < NBOX; box += THREADS) {
            const float mys = s[box];
            int rank = 0;
            #pragma unroll 4
            for (int k = 0; k < NBOX; k++) {
                float sk = s[k];
                rank += (sk > mys) || (sk == mys && k < box);
            }
            const float* bp = boxes + (size_t)(b * NBOX + box) * 4;
            bx[rank]  = make_float4(bp[0], bp[1], bp[2], bp[3]);
            val[rank] = (mys > CONF_THRS) ? 1 : 0;
        }
        __syncthreads();

        if (tid < NWORDS) {
            unsigned int w = 0;
            for (int jj = 0; jj < 32; jj++) {
                int j = tid * 32 + jj;
                if (j < NBOX && val[j]) w |= (1u << jj);
            }
            keepW[tid] = w;
        }
        __syncthreads();

        // lazy greedy NMS: block-wide ballot per kept candidate.
        // thread handles j1 = tid (words 0..7) and j2 = 256+tid (words 8,9).
        {
            int cnt = 0;
            int i = -1;
            while (cnt < RSEL) {
                int ni = -1;
                {
                    int wstart = (i + 1) >> 5;
                    for (int w = wstart; w < NWORDS; w++) {
                        unsigned int word = keepW[w];
                        if (w == wstart) {
                            int bit = (i + 1) & 31;
                            word &= ~((bit ? (1u << bit) : 1u) - 1u);
                        }
                        if (word) { ni = (w << 5) + __ffs(word) - 1; break; }
                    }
                }
                if (ni < 0) break;
                i = ni;
                cnt++;

                const float4 a = bx[i];
                bool sup1 = false, sup2 = false;
                if (tid > i && tid < NBOX)               sup1 = iou_gt(a, bx[tid]);
                const int j2 = THREADS + tid;
                if (j2 > i && j2 < NBOX)                 sup2 = iou_gt(a, bx[j2]);

                unsigned int bal1 = __ballot_sync(0xffffffffu, sup1);
                unsigned int bal2 = __ballot_sync(0xffffffffu, sup2);
                if (lane == 0) {
                    if (bal1)              keepW[warp]     &= ~bal1;  // words 0..7
                    if (bal2 && warp < 2)  keepW[8 + warp] &= ~bal2;  // words 8,9
                }
                __syncthreads();
            }
        }

        // stable partition select
        for (int i = tid; i < NBOX; i += THREADS) {
            const int w = i >> 5, bit = i & 31;
            int kept_before = 0;
            for (int q = 0; q < w; q++) kept_before += __popc(keepW[q]);
            kept_before += __popc(keepW[w] & ((1u << bit) - 1u));
            const bool mykeep = (keepW[w] >> bit) & 1u;
            int totKept = 0;
            for (int q = 0; q < NWORDS; q++) totKept += __popc(keepW[q]);

            int pos = mykeep ? kept_before : (totKept + (i - kept_before));
            if (pos < RSEL) {
                float4 bb = bx[i];
                sselBox[pos]   = bb;
                sselValid[pos] = mykeep ? 1 : 0;
                float dx = __fsub_rn(bb.z, bb.x), dy = __fsub_rn(bb.w, bb.y);
                float ss = __fadd_rn(__fmul_rn(dx, dx), __fmul_rn(dy, dy));
                float size = sqrtf(fmaxf(ss, 1e-12f));
                float tt = floorf(__fadd_rn(4.0f, log2f(__fmul_rn(__fdiv_rn(size, 224.0f), 4.0f))));
                tt = fminf(fmaxf(tt, 2.0f), 5.0f);
                sselLv[pos] = (int)tt - 2;
            }
        }
        __syncthreads();

        // per-ROI pooling plan
        if (tid < RSEL) {
            const int rr  = tid;
            const int roi = b * RSEL + rr;

            float wx[MAXSPAN];
            #pragma unroll
            for (int q = 0; q < MAXSPAN; q++) wx[q] = 0.0f;

            int Kr = 0, xmin = 0, xmax = -1;
            const int lv = sselLv[rr];
            int   rows[MAXROWS];
            float rwt[MAXROWS];

            if (sselValid[rr]) {
                const int Hs[4] = {200, 100, 50, 25};
                const int H = Hs[lv], W = H;
                const float4 bb = sselBox[rr];
                const float rw = fmaxf(__fsub_rn(bb.z, bb.x), 1.0f);
                const float rh = fmaxf(__fsub_rn(bb.w, bb.y), 1.0f);

                int xm = 0x7fffffff, xM = -1;
                int ix0s[GRIDP], ix1s[GRIDP];
                float lxs[GRIDP], mxs[GRIDP];
                for (int k = 0; k < GRIDP; k++) {
                    float g = (k + 0.5f) / (float)GRIDP;
                    float X = __fadd_rn(bb.x, __fmul_rn(rw, g));
                    float mx = (X < -1.0f || X > (float)W) ? 0.0f : 1.0f;
                    float x = fminf(fmaxf(X, 0.0f), (float)(W - 1));
                    int i0 = (int)floorf(x);
                    int i1 = min(i0 + 1, W - 1);
                    ix0s[k] = i0; ix1s[k] = i1;
                    lxs[k] = __fsub_rn(x, (float)i0); mxs[k] = mx;
                    if (mx > 0.0f) { if (i0 < xm) xm = i0; if (i1 > xM) xM = i1; }
                }
                if (xM >= xm && (xM - xm) < MAXSPAN) {
                    for (int k = 0; k < GRIDP; k++) {
                        if (mxs[k] == 0.0f) continue;
                        wx[ix0s[k] - xm] += __fmul_rn(1.0f - lxs[k], mxs[k]);
                        wx[ix1s[k] - xm] += __fmul_rn(lxs[k], mxs[k]);
                    }
                    xmin = xm; xmax = xM;

                    for (int k = 0; k < GRIDP; k++) {
                        float g = (k + 0.5f) / (float)GRIDP;
                        float Y = __fadd_rn(bb.y, __fmul_rn(rh, g));
                        float my = (Y < -1.0f || Y > (float)H) ? 0.0f : 1.0f;
                        float y = fminf(fmaxf(Y, 0.0f), (float)(H - 1));
                        int iy0 = (int)floorf(y);
                        int iy1 = min(iy0 + 1, H - 1);
                        float ly = __fsub_rn(y, (float)iy0);
                        float w0 = __fmul_rn(1.0f - ly, my);
                        float w1 = __fmul_rn(ly, my);
                        for (int tt = 0; tt < 2; tt++) {
                            int   row = tt ? iy1 : iy0;
                            float wv  = tt ? w1 : w0;
                            if (wv == 0.0f) continue;
                            int found = -1;
                            for (int q = 0; q < Kr; q++)
                                if (rows[q] == row) { found = q; break; }
                            if (found >= 0) rwt[found] += wv;
                            else if (Kr < MAXROWS) { rows[Kr] = row; rwt[Kr] = wv; Kr++; }
                        }
                    }
                }
            }

            for (int q = 0; q < MAXSPAN; q++) g_wx[roi][q] = wx[q];
            for (int q = 0; q < MAXROWS; q++) {
                g_rows[roi][q] = (q < Kr) ? rows[q] : 0;
                g_rwt[roi][q]  = (q < Kr) ? rwt[q]  : 0.0f;
            }
            g_meta[roi] = make_int4(Kr, xmin, xmax, lv);
        }

        // publish plan
        __threadfence();
        __syncthreads();
        if (tid == 0) atomicExch(&g_ready[b], 1);
    } else {
        // wait for this batch's plan (selector is wave-1 resident -> progress)
        if (tid == 0) {
            while (__ldcg(&g_ready[b]) == 0) __nanosleep(128);
        }
        __syncthreads();
    }

    // ================= pooling (all blocks) =================
    const int roi = b * RSEL + r;

    if (tid < MAXSPAN)                          swx[tid] = __ldcg(&g_wx[roi][tid]);
    else if (tid < MAXSPAN + MAXROWS)           srows[tid - MAXSPAN] = __ldcg(&g_rows[roi][tid - MAXSPAN]);
    else if (tid < MAXSPAN + 2 * MAXROWS)       srwt[tid - MAXSPAN - MAXROWS] = __ldcg(&g_rwt[roi][tid - MAXSPAN - MAXROWS]);
    else if (tid == MAXSPAN + 2 * MAXROWS)      smeta = __ldcg(&g_meta[roi]);
    __syncthreads();

    const int Kr   = smeta.x;
    const int xmin = smeta.y;
    const int xmax = smeta.z;
    const int lv   = smeta.w;

    const int Hs[4] = {200, 100, 50, 25};
    const int H = Hs[lv], W = H;
    const float* fbase =
        (lv == 0 ? f0 : lv == 1 ? f1 : lv == 2 ? f2 : f3) + (size_t)b * CCH * H * W;

    const int c = z * 8 + warp;
    const float* cp = fbase + (size_t)c * H * W;

    const int x0 = xmin + lane;
    const int x1 = x0 + 32;
    const bool a0 = (x0 <= xmax);
    const bool a1 = (x1 <= xmax);
    const float w0 = a0 ? swx[lane] : 0.0f;
    const float w1 = a1 ? swx[lane + 32] : 0.0f;

    float acc = 0.0f;
    #pragma unroll 4
    for (int j = 0; j < Kr; j++) {
        const float* rp = cp + srows[j] * W;
        float sv = 0.0f;
        if (a0) sv = rp[x0] * w0;
        if (a1) sv += rp[x1] * w1;
        acc += srwt[j] * sv;
    }

    #pragma unroll
    for (int o = 16; o > 0; o >>= 1)
        acc += __shfl_xor_sync(0xffffffffu, acc, o);

    if (lane == 0)
        out[(size_t)roi * CCH + c] = acc * (1.0f / 196.0f);
}

// ---------------------------------------------------------------------------
extern "C" void kernel_launch(void* const* d_in, const int* in_sizes, int n_in,
                              void* d_out, int out_size)
{
    const float* boxes  = (const float*)d_in[0];
    const float* scores = (const float*)d_in[1];
    const float* f0     = (const float*)d_in[2];
    const float* f1     = (const float*)d_in[3];
    const float* f2     = (const float*)d_in[4];
    const float* f3     = (const float*)d_in[5];
    float* out = (float*)d_out;

    fused_kernel<<<dim3(RSEL, BB, 32), THREADS>>>(boxes, scores, f0, f1, f2, f3, out);
}

// round 15
// speedup vs baseline: 1.3817x; 1.3817x over previous
#include <cuda_runtime.h>
#include <math.h>

#define BB 8
#define NBOX 300
#define RSEL 36
#define CCH 256
#define NROI (BB * RSEL)
#define IOU_THRS 0.7f
#define CONF_THRS 0.3f
#define GRIDP 14     // OUT*SR
#define NWORDS 10    // ceil(300/32)
#define MAXROWS 28
#define MAXSPAN 64
#define SELTHR 1024

// ---- per-ROI pooling plan (device scratch; no allocs) ----
__device__ float g_wx[NROI][MAXSPAN];
__device__ int   g_rows[NROI][MAXROWS];
__device__ float g_rwt[NROI][MAXROWS];
__device__ int4  g_meta[NROI];        // {Kr, xmin, xmax, lv}

__device__ __forceinline__ float neg_inf() { return __int_as_float(0xff800000); }

__device__ __forceinline__ bool iou_gt(const float4 a, const float4 bb)
{
    float areaA = __fmul_rn(__fsub_rn(a.z, a.x), __fsub_rn(a.w, a.y));
    float areaB = __fmul_rn(__fsub_rn(bb.z, bb.x), __fsub_rn(bb.w, bb.y));
    float ltx = fmaxf(a.x, bb.x), lty = fmaxf(a.y, bb.y);
    float rbx = fminf(a.z, bb.z), rby = fminf(a.w, bb.w);
    float iw = fmaxf(__fsub_rn(rbx, ltx), 0.0f);
    float ih = fmaxf(__fsub_rn(rby, lty), 0.0f);
    float inter = __fmul_rn(iw, ih);
    float den = __fadd_rn(__fsub_rn(__fadd_rn(areaA, areaB), inter), 1e-9f);
    return __fdiv_rn(inter, den) > IOU_THRS;
}

// ---------------------------------------------------------------------------
// Kernel A: sort (3-way split rank) + ballot NMS + partition + WARP-PARALLEL
// per-ROI prep (no local-memory arrays). One block per batch, 1024 threads.
// ---------------------------------------------------------------------------
__global__ void __launch_bounds__(SELTHR)
select_kernel(const float* __restrict__ boxes,
              const float* __restrict__ scores)
{
    const int b   = blockIdx.x;
    const int tid = threadIdx.x;
    const int lane = tid & 31;
    const int warp = tid >> 5;

    __shared__ float         s[NBOX];
    __shared__ float4        bx[NBOX];
    __shared__ unsigned char val[NBOX];
    __shared__ short         pr[2][NBOX];
    __shared__ unsigned int  keepW[NWORDS];
    __shared__ float4 sselBox[RSEL];
    __shared__ int    sselLv[RSEL];
    __shared__ int    sselValid[RSEL];

    if (tid < NBOX) {
        float sc = scores[b * NBOX + tid];
        s[tid] = (sc > CONF_THRS) ? sc : neg_inf();
    }
    __syncthreads();

    // ---- 3-way split stable-descending rank (100 elems per thread) ----
    int myrk = 0;
    if (tid < 3 * NBOX) {
        const int g   = tid / NBOX;          // 0,1,2
        const int box = tid - g * NBOX;
        const int k0 = g * 100, k1 = k0 + 100;
        const float mys = s[box];
        #pragma unroll 4
        for (int k = k0; k < k1; k++) {
            float sk = s[k];
            myrk += (sk > mys) || (sk == mys && k < box);
        }
        if (g) pr[g - 1][box] = (short)myrk;
    }
    __syncthreads();

    if (tid < NBOX) {
        const int rank = myrk + (int)pr[0][tid] + (int)pr[1][tid];
        const float* bp = boxes + (size_t)(b * NBOX + tid) * 4;
        bx[rank]  = make_float4(bp[0], bp[1], bp[2], bp[3]);
        val[rank] = (s[tid] > CONF_THRS) ? 1 : 0;
    }
    __syncthreads();

    // ---- initial keep bits ----
    if (tid < NWORDS) {
        unsigned int w = 0;
        for (int jj = 0; jj < 32; jj++) {
            int j = tid * 32 + jj;
            if (j < NBOX && val[j]) w |= (1u << jj);
        }
        keepW[tid] = w;
    }
    __syncthreads();

    // ---- lazy greedy NMS: block-wide ballot per kept candidate ----
    {
        int cnt = 0;
        int i = -1;
        while (cnt < RSEL) {
            int ni = -1;
            {
                int wstart = (i + 1) >> 5;
                for (int w = wstart; w < NWORDS; w++) {
                    unsigned int word = keepW[w];
                    if (w == wstart) {
                        int bit = (i + 1) & 31;
                        word &= ~((bit ? (1u << bit) : 1u) - 1u);
                    }
                    if (word) { ni = (w << 5) + __ffs(word) - 1; break; }
                }
            }
            if (ni < 0) break;
            i = ni;
            cnt++;

            bool sup = false;
            if (tid > i && tid < NBOX) sup = iou_gt(bx[i], bx[tid]);
            unsigned int bal = __ballot_sync(0xffffffffu, sup);
            if (lane == 0 && warp < NWORDS && bal)
                keepW[warp] &= ~bal;
            __syncthreads();
        }
    }

    // ---- stable partition select ----
    if (tid < NBOX) {
        const int w = tid >> 5, bit = tid & 31;
        int kept_before = 0;
        for (int q = 0; q < w; q++) kept_before += __popc(keepW[q]);
        kept_before += __popc(keepW[w] & ((1u << bit) - 1u));
        const bool mykeep = (keepW[w] >> bit) & 1u;
        int totKept = 0;
        for (int q = 0; q < NWORDS; q++) totKept += __popc(keepW[q]);

        int pos = mykeep ? kept_before : (totKept + (tid - kept_before));
        if (pos < RSEL) {
            float4 bb = bx[tid];
            sselBox[pos]   = bb;
            sselValid[pos] = mykeep ? 1 : 0;
            float dx = __fsub_rn(bb.z, bb.x), dy = __fsub_rn(bb.w, bb.y);
            float ss = __fadd_rn(__fmul_rn(dx, dx), __fmul_rn(dy, dy));
            float size = sqrtf(fmaxf(ss, 1e-12f));
            float tt = floorf(__fadd_rn(4.0f, log2f(__fmul_rn(__fdiv_rn(size, 224.0f), 4.0f))));
            tt = fminf(fmaxf(tt, 2.0f), 5.0f);
            sselLv[pos] = (int)tt - 2;
        }
    }
    __syncthreads();

    // ---- WARP-PARALLEL per-ROI prep: one warp per ROI, registers only ----
    for (int r = warp; r < RSEL; r += 32) {
        const int roi = b * RSEL + r;
        const int lv  = sselLv[r];
        const bool v  = sselValid[r] != 0;
        const float4 bb = sselBox[r];

        const int Hs[4] = {200, 100, 50, 25};
        const int H = Hs[lv], W = H;
        const float rw = fmaxf(__fsub_rn(bb.z, bb.x), 1.0f);
        const float rh = fmaxf(__fsub_rn(bb.w, bb.y), 1.0f);

        // per-lane tap k = lane (valid for lane < GRIDP)
        int   i0 = 0, i1 = 0, y0 = 0, y1r = 0;
        float w0 = 0.f, w1 = 0.f, wy0 = 0.f, wy1 = 0.f;
        int   xminc = 0x7fffffff, xmaxc = -1, yminc = 0x7fffffff;
        if (v && lane < GRIDP) {
            float g = (lane + 0.5f) / (float)GRIDP;
            // x tap
            float X  = __fadd_rn(bb.x, __fmul_rn(rw, g));
            float mx = (X < -1.0f || X > (float)W) ? 0.0f : 1.0f;
            float x  = fminf(fmaxf(X, 0.0f), (float)(W - 1));
            i0 = (int)floorf(x);
            i1 = min(i0 + 1, W - 1);
            float lx = __fsub_rn(x, (float)i0);
            w0 = __fmul_rn(1.0f - lx, mx);
            w1 = __fmul_rn(lx, mx);
            if (mx > 0.0f) { xminc = i0; xmaxc = i1; }
            // y tap
            float Y  = __fadd_rn(bb.y, __fmul_rn(rh, g));
            float my = (Y < -1.0f || Y > (float)H) ? 0.0f : 1.0f;
            float y  = fminf(fmaxf(Y, 0.0f), (float)(H - 1));
            y0  = (int)floorf(y);
            y1r = min(y0 + 1, H - 1);
            float ly = __fsub_rn(y, (float)y0);
            wy0 = __fmul_rn(1.0f - ly, my);
            wy1 = __fmul_rn(ly, my);
            yminc = y0;
        }
        // warp reductions for xmin/xmax/ymin
        #pragma unroll
        for (int o = 16; o > 0; o >>= 1) {
            xminc = min(xminc, __shfl_xor_sync(0xffffffffu, xminc, o));
            xmaxc = max(xmaxc, __shfl_xor_sync(0xffffffffu, xmaxc, o));
            yminc = min(yminc, __shfl_xor_sync(0xffffffffu, yminc, o));
        }

        const bool spanok = v && (xmaxc >= xminc);

        // ordered owner-scan: lane owns span slots {lane, lane+32}
        float wxA = 0.f, wxB = 0.f, wyA = 0.f, wyB = 0.f;
        if (spanok) {
            #pragma unroll
            for (int k = 0; k < GRIDP; k++) {
                int   i0k = __shfl_sync(0xffffffffu, i0, k);
                int   i1k = __shfl_sync(0xffffffffu, i1, k);
                float w0k = __shfl_sync(0xffffffffu, w0, k);
                float w1k = __shfl_sync(0xffffffffu, w1, k);
                float mxk = w0k + w1k;    // >0 iff mx>0 (w0+w1 = mx)
                if (mxk > 0.0f) {
                    int s0 = i0k - xminc, s1 = i1k - xminc;
                    if (s0 == lane)          wxA += w0k;
                    else if (s0 == lane + 32) wxB += w0k;
                    if (s1 == lane)          wxA += w1k;
                    else if (s1 == lane + 32) wxB += w1k;
                }
                int   y0k  = __shfl_sync(0xffffffffu, y0, k);
                int   y1k  = __shfl_sync(0xffffffffu, y1r, k);
                float wy0k = __shfl_sync(0xffffffffu, wy0, k);
                float wy1k = __shfl_sync(0xffffffffu, wy1, k);
                if (wy0k > 0.0f) {
                    int t0 = y0k - yminc;
                    if (t0 == lane)           wyA += wy0k;
                    else if (t0 == lane + 32) wyB += wy0k;
                }
                if (wy1k > 0.0f) {
                    int t1 = y1k - yminc;
                    if (t1 == lane)           wyA += wy1k;
                    else if (t1 == lane + 32) wyB += wy1k;
                }
            }
        }

        // write dense x-weights (slots beyond span are zero)
        g_wx[roi][lane]      = wxA;
        g_wx[roi][lane + 32] = wxB;

        // compact nonzero row slots (ascending, matches reference order)
        unsigned int mA = __ballot_sync(0xffffffffu, wyA > 0.0f);
        unsigned int mB = __ballot_sync(0xffffffffu, wyB > 0.0f);
        int Kr = __popc(mA) + __popc(mB);
        if (wyA > 0.0f) {
            int p = __popc(mA & ((1u << lane) - 1u));
            g_rows[roi][p] = yminc + lane;
            g_rwt[roi][p]  = wyA;
        }
        if (wyB > 0.0f) {
            int p = __popc(mA) + __popc(mB & ((1u << lane) - 1u));
            g_rows[roi][p] = yminc + lane + 32;
            g_rwt[roi][p]  = wyB;
        }
        for (int q = Kr + lane; q < MAXROWS; q += 32) {
            g_rows[roi][q] = 0;
            g_rwt[roi][q]  = 0.0f;
        }
        if (lane == 0)
            g_meta[roi] = spanok ? make_int4(Kr, xminc, xmaxc, lv)
                                 : make_int4(0, 0, -1, lv);
    }
}

// ---------------------------------------------------------------------------
// Kernel B: pooling. One warp per (roi, channel). grid (RSEL, BB, 32).
// (proven 22.6-22.9us configuration — unchanged)
// ---------------------------------------------------------------------------
__global__ void __launch_bounds__(256)
pool_kernel(const float* __restrict__ f0,
            const float* __restrict__ f1,
            const float* __restrict__ f2,
            const float* __restrict__ f3,
            float* __restrict__ out)
{
    const int r = blockIdx.x, b = blockIdx.y;
    const int roi = b * RSEL + r;
    const int tid = threadIdx.x;
    const int warp = tid >> 5, lane = tid & 31;

    __shared__ float swx[MAXSPAN];
    __shared__ int   srows[MAXROWS];
    __shared__ float srwt[MAXROWS];
    __shared__ int4  smeta;

    if (tid < MAXSPAN)                          swx[tid] = g_wx[roi][tid];
    else if (tid < MAXSPAN + MAXROWS)           srows[tid - MAXSPAN] = g_rows[roi][tid - MAXSPAN];
    else if (tid < MAXSPAN + 2 * MAXROWS)       srwt[tid - MAXSPAN - MAXROWS] = g_rwt[roi][tid - MAXSPAN - MAXROWS];
    else if (tid == MAXSPAN + 2 * MAXROWS)      smeta = g_meta[roi];
    __syncthreads();

    const int Kr   = smeta.x;
    const int xmin = smeta.y;
    const int xmax = smeta.z;
    const int lv   = smeta.w;

    const int Hs[4] = {200, 100, 50, 25};
    const int H = Hs[lv], W = H;
    const float* fbase =
        (lv == 0 ? f0 : lv == 1 ? f1 : lv == 2 ? f2 : f3) + (size_t)b * CCH * H * W;

    const int c = blockIdx.z * 8 + warp;
    const float* cp = fbase + (size_t)c * H * W;

    const int x0 = xmin + lane;
    const int x1 = x0 + 32;
    const bool a0 = (x0 <= xmax);
    const bool a1 = (x1 <= xmax);
    const float w0 = a0 ? swx[lane] : 0.0f;
    const float w1 = a1 ? swx[lane + 32] : 0.0f;

    float acc = 0.0f;
    #pragma unroll 4
    for (int j = 0; j < Kr; j++) {
        const float* rp = cp + srows[j] * W;
        float s = 0.0f;
        if (a0) s = rp[x0] * w0;
        if (a1) s += rp[x1] * w1;
        acc += srwt[j] * s;
    }

    #pragma unroll
    for (int o = 16; o > 0; o >>= 1)
        acc += __shfl_xor_sync(0xffffffffu, acc, o);

    if (lane == 0)
        out[(size_t)roi * CCH + c] = acc * (1.0f / 196.0f);
}

// ---------------------------------------------------------------------------
extern "C" void kernel_launch(void* const* d_in, const int* in_sizes, int n_in,
                              void* d_out, int out_size)
{
    const float* boxes  = (const float*)d_in[0];
    const float* scores = (const float*)d_in[1];
    const float* f0     = (const float*)d_in[2];
    const float* f1     = (const float*)d_in[3];
    const float* f2     = (const float*)d_in[4];
    const float* f3     = (const float*)d_in[5];
    float* out = (float*)d_out;

    select_kernel<<<BB, SELTHR>>>(boxes, scores);
    pool_kernel<<<dim3(RSEL, BB, 32), 256>>>(f0, f1, f2, f3, out);
}